// round 1
// baseline (speedup 1.0000x reference)
#include <cuda_runtime.h>
#include <cuda_bf16.h>

#define BATCH 8
#define CH    3
#define TT    16
#define H     512
#define WID   512
#define S     224
#define RMAXF 1024.0f

// One thread per output pixel. blockDim = (32, 8) -> 256 threads.
// grid = (ceil(224/32)=7, ceil(224/8)=28, B*C*T=384 planes).
__global__ __launch_bounds__(256) void crop_prompter_kernel(
    const float* __restrict__ x,
    const int*   __restrict__ cam_views,
    const float* __restrict__ resize,
    const float* __restrict__ yoffs,
    const float* __restrict__ xoffs,
    float*       __restrict__ out)
{
    const int xs = blockIdx.x * 32 + threadIdx.x;
    const int ys = blockIdx.y * 8  + threadIdx.y;
    if (xs >= S || ys >= S) return;

    const int plane = blockIdx.z;           // b*C*T + c*T + t
    const int b     = plane / (CH * TT);

    // Per-camera params (tiny arrays; L1/const-cache resident)
    const int   cam   = __ldg(&cam_views[b]);
    const float r     = floorf(fminf(fmaxf(__ldg(&resize[cam]), (float)H), RMAXF));
    const float scale = (float)H / r;       // in [0.5, 1.0]
    const float yo    = floorf(fminf(fmaxf(__ldg(&yoffs[cam]), 0.0f), r - (float)S));
    const float xo    = floorf(fminf(fmaxf(__ldg(&xoffs[cam]), 0.0f), r - (float)S));

    // Source coords (align_corners=False), clamped at 0 like torch
    const float sy = fmaxf((yo + (float)ys + 0.5f) * scale - 0.5f, 0.0f);
    const float sx = fmaxf((xo + (float)xs + 0.5f) * scale - 0.5f, 0.0f);

    int y0 = (int)sy;  if (y0 > H - 1) y0 = H - 1;   // sy >= 0 so cast == floor
    int x0 = (int)sx;  if (x0 > WID - 1) x0 = WID - 1;
    const int y1 = min(y0 + 1, H - 1);
    const int x1 = min(x0 + 1, WID - 1);
    const float wy = sy - (float)y0;
    const float wx = sx - (float)x0;

    const float* p = x + (size_t)plane * (H * WID);
    const float a00 = __ldg(p + y0 * WID + x0);
    const float a01 = __ldg(p + y0 * WID + x1);
    const float a10 = __ldg(p + y1 * WID + x0);
    const float a11 = __ldg(p + y1 * WID + x1);

    // match reference order: interpolate rows over y first, then over x
    const float v0  = a00 * (1.0f - wy) + a10 * wy;
    const float v1  = a01 * (1.0f - wy) + a11 * wy;
    const float val = v0 * (1.0f - wx) + v1 * wx;

    out[(size_t)plane * (S * S) + (size_t)ys * S + xs] = val;
}

extern "C" void kernel_launch(void* const* d_in, const int* in_sizes, int n_in,
                              void* d_out, int out_size)
{
    const float* x    = (const float*)d_in[0];
    const int*   cams = (const int*)  d_in[1];
    const float* rz   = (const float*)d_in[2];
    const float* yo   = (const float*)d_in[3];
    const float* xo   = (const float*)d_in[4];
    float* out = (float*)d_out;

    dim3 block(32, 8, 1);
    dim3 grid((S + 31) / 32, (S + 7) / 8, BATCH * CH * TT);
    crop_prompter_kernel<<<grid, block>>>(x, cams, rz, yo, xo, out);
}

// round 2
// speedup vs baseline: 2.2321x; 2.2321x over previous
#include <cuda_runtime.h>
#include <cuda_bf16.h>

#define BATCH 8
#define CH    3
#define TT    16
#define H     512
#define WID   512
#define S     224
#define RMAXF 1024.0f

// One warp per output row: 32 lanes x 7 iterations cover 224 pixels.
// blockDim = (32, 8): 8 rows per block. grid = (1, 28, 384 planes).
__global__ __launch_bounds__(256) void crop_prompter_kernel(
    const float* __restrict__ x,
    const int*   __restrict__ cam_views,
    const float* __restrict__ resize,
    const float* __restrict__ yoffs,
    const float* __restrict__ xoffs,
    float*       __restrict__ out)
{
    const int plane = blockIdx.z;                 // b*C*T + c*T + t
    const int b     = plane / (CH * TT);          // constant-div -> mulhi
    const int ys    = blockIdx.y * 8 + threadIdx.y;   // 28*8 == 224, no guard
    const int tx    = threadIdx.x;

    // Per-camera params (computed once per thread, not per pixel)
    const int   cam   = __ldg(&cam_views[b]);
    const float r     = floorf(fminf(fmaxf(__ldg(&resize[cam]), (float)H), RMAXF));
    const float scale = (float)H / r;             // in [0.5, 1.0]
    const float yo    = floorf(fminf(fmaxf(__ldg(&yoffs[cam]), 0.0f), r - (float)S));
    const float xo    = floorf(fminf(fmaxf(__ldg(&xoffs[cam]), 0.0f), r - (float)S));

    // Row (y) sampling — constant across the whole output row
    const float sy = fmaxf((yo + (float)ys + 0.5f) * scale - 0.5f, 0.0f);
    int y0 = (int)sy; if (y0 > H - 1) y0 = H - 1;
    const int   y1     = min(y0 + 1, H - 1);
    const float wy     = sy - (float)y0;
    const float one_wy = 1.0f - wy;

    const float* __restrict__ p  = x + (size_t)plane * (H * WID);
    const float* __restrict__ r0 = p + (size_t)y0 * WID;
    const float* __restrict__ r1 = p + (size_t)y1 * WID;
    float* __restrict__ orow = out + (size_t)plane * (S * S) + (size_t)ys * S;

    // Column (x) sampling: sx advances by 32*scale per iteration.
    // Base is clamped once; step > 0 keeps sx >= 0 afterwards.
    float sx = fmaxf((xo + (float)tx + 0.5f) * scale - 0.5f, 0.0f);
    const float step = 32.0f * scale;

    #pragma unroll
    for (int i = 0; i < 7; ++i) {
        int x0 = (int)sx;                 // sx >= 0 -> cast == floor
        if (x0 > WID - 1) x0 = WID - 1;
        const int   x1 = min(x0 + 1, WID - 1);
        const float wx = sx - (float)x0;

        const float a00 = __ldg(r0 + x0);
        const float a01 = __ldg(r0 + x1);
        const float a10 = __ldg(r1 + x0);
        const float a11 = __ldg(r1 + x1);

        const float v0 = a00 * one_wy + a10 * wy;   // lerp over y first (ref order)
        const float v1 = a01 * one_wy + a11 * wy;
        orow[tx + 32 * i] = v0 * (1.0f - wx) + v1 * wx;

        sx += step;
    }
}

extern "C" void kernel_launch(void* const* d_in, const int* in_sizes, int n_in,
                              void* d_out, int out_size)
{
    const float* x    = (const float*)d_in[0];
    const int*   cams = (const int*)  d_in[1];
    const float* rz   = (const float*)d_in[2];
    const float* yo   = (const float*)d_in[3];
    const float* xo   = (const float*)d_in[4];
    float* out = (float*)d_out;

    dim3 block(32, 8, 1);
    dim3 grid(1, S / 8, BATCH * CH * TT);
    crop_prompter_kernel<<<grid, block>>>(x, cams, rz, yo, xo, out);
}